// round 16
// baseline (speedup 1.0000x reference)
#include <cuda_runtime.h>

// ---------------------------------------------------------------------------
// LaplacianRegularization — single fused persistent kernel.
//   degree = segment_sum(w, row);  ys = y * rsqrt(degree)[:,None]
//   out = mean_e( ||ys[row] - ys[col]||_2 * w_e )
//
// Inputs (metadata order):
//   d_in[0] : edge_index  int64 OR int32 (2, E)   (dtype probed per block)
//   d_in[1] : edge_weights float32 (E,)
//   d_in[2] : y            float32 (N, 16)
// Output: 1 float
//
// Grid = 592 blocks of 256 (__launch_bounds__(256,4) => <=64 regs => 4 CTAs/SM
// co-resident on 148 SMs; also fits 152-SM GB300). Device-wide ticket+spin
// barriers separate: [probe] -> A: degree atomics -> B: ys scale (+re-zero
// deg) -> C: persistent quad-gather edge loop -> finalize (last ticket).
// All scratch invariants are restored in-kernel => graph-replay safe.
// ---------------------------------------------------------------------------

#define MAX_NODES      131072
#define EDGES_PER_TILE 256
#define NBLOCKS        592
#define NTHREADS       256

__device__ float    g_deg[MAX_NODES];     // zero-init; re-zeroed in phase B
__device__ float4   g_ys[MAX_NODES * 4];  // scaled fp32 rows (64B each)
__device__ double   g_sum;                // reset by finalize
__device__ unsigned g_count;              // reset by finalize
__device__ unsigned g_bar1, g_bar2;       // reset by finalize

__device__ __forceinline__ float ldcg_f(const float* p) {
    float v;
    asm volatile("ld.global.cg.f32 %0, [%1];" : "=f"(v) : "l"(p));
    return v;
}

__device__ __forceinline__ void grid_barrier(unsigned* bar) {
    __threadfence();
    __syncthreads();
    if (threadIdx.x == 0) {
        atomicAdd(bar, 1u);
        while (*(volatile unsigned*)bar < gridDim.x) __nanosleep(64);
    }
    __syncthreads();
    __threadfence();
}

__global__ void __launch_bounds__(NTHREADS, 4)
k_fused(const void* __restrict__ ei,
        const float* __restrict__ w,
        const float4* __restrict__ y4,
        float* __restrict__ out, int E, int N, int ntiles) {
    const int gtid    = blockIdx.x * NTHREADS + threadIdx.x;
    const int gstride = gridDim.x * NTHREADS;

    // ---- per-block dtype probe ---------------------------------------------
    // int64 indices < 2^31 have zero hi-words; for int32 the odd 32-bit words
    // are node ids, nonzero w.h.p. over 512 samples of U[0, N).
    __shared__ unsigned s_flag;
    if (threadIdx.x == 0) s_flag = 0u;
    __syncthreads();
    {
        const unsigned* words = (const unsigned*)ei;
        int samples = E < 512 ? E : 512;
        unsigned v = 0;
        for (int i = threadIdx.x; i < samples; i += NTHREADS)
            v |= words[2 * i + 1];
        if (v) atomicOr(&s_flag, 1u);
    }
    __syncthreads();
    const bool is32 = (s_flag != 0u);

    // ---- phase A: degree = segment_sum(w, row) ------------------------------
    for (int e = gtid; e < E; e += gstride) {
        int r = is32 ? ((const int*)ei)[e] : (int)((const long long*)ei)[e];
        if ((unsigned)r < (unsigned)N)
            atomicAdd(&g_deg[r], w[e]);
    }

    grid_barrier(&g_bar1);

    // ---- phase B: ys = y * rsqrt(degree); re-zero g_deg ----------------------
    // One thread per float4; the 4 lanes of a node are in one warp (gstride is
    // a multiple of 4), so the broadcast deg load precedes the lane-0 zero.
    for (int i = gtid; i < N * 4; i += gstride) {
        int node = i >> 2;
        float s = rsqrtf(ldcg_f(&g_deg[node]));   // L2-coherent read of atomics
        if ((i & 3) == 0) g_deg[node] = 0.0f;     // restore invariant
        float4 v = __ldg(y4 + i);
        v.x *= s; v.y *= s; v.z *= s; v.w *= s;
        g_ys[i] = v;
    }

    grid_barrier(&g_bar2);

    // ---- phase C: quad-gather edge loop --------------------------------------
    const int lane4 = threadIdx.x & 3;
    const int qid   = threadIdx.x >> 2;
    float val = 0.0f;

    for (int tile = blockIdx.x; tile < ntiles; tile += gridDim.x) {
        const long long base = (long long)tile * EDGES_PER_TILE + (long long)qid * 4;

        int   r[4], c[4];
        float we[4];
        bool  full = (base + 3 < (long long)E);

        if (full) {
            if (is32) {
                const int4 rv = __ldg((const int4*)((const int*)ei + base));
                const int4 cv = __ldg((const int4*)((const int*)ei + (long long)E + base));
                r[0] = rv.x; r[1] = rv.y; r[2] = rv.z; r[3] = rv.w;
                c[0] = cv.x; c[1] = cv.y; c[2] = cv.z; c[3] = cv.w;
            } else {
                const longlong2 r01 = __ldg((const longlong2*)((const long long*)ei + base));
                const longlong2 r23 = __ldg((const longlong2*)((const long long*)ei + base + 2));
                const longlong2 c01 = __ldg((const longlong2*)((const long long*)ei + (long long)E + base));
                const longlong2 c23 = __ldg((const longlong2*)((const long long*)ei + (long long)E + base + 2));
                r[0] = (int)r01.x; r[1] = (int)r01.y; r[2] = (int)r23.x; r[3] = (int)r23.y;
                c[0] = (int)c01.x; c[1] = (int)c01.y; c[2] = (int)c23.x; c[3] = (int)c23.y;
            }
            const float4 wv = __ldg((const float4*)(w + base));
            we[0] = wv.x; we[1] = wv.y; we[2] = wv.z; we[3] = wv.w;
        } else {
            #pragma unroll
            for (int k = 0; k < 4; k++) {
                long long e = base + k;
                if (e < (long long)E) {
                    r[k]  = is32 ? ((const int*)ei)[e] : (int)((const long long*)ei)[e];
                    c[k]  = is32 ? ((const int*)ei)[(long long)E + e]
                                 : (int)((const long long*)ei)[(long long)E + e];
                    we[k] = w[e];
                } else { r[k] = -1; c[k] = -1; we[k] = 0.0f; }
            }
        }

        // 8 independent random row-gathers per thread (front-batched MLP).
        float4 a[4], b[4];
        #pragma unroll
        for (int k = 0; k < 4; k++) {
            bool ok = ((unsigned)r[k] < (unsigned)N) && ((unsigned)c[k] < (unsigned)N);
            if (ok) {
                a[k] = g_ys[(size_t)r[k] * 4 + lane4];
                b[k] = g_ys[(size_t)c[k] * 4 + lane4];
            } else {
                a[k] = make_float4(0, 0, 0, 0);
                b[k] = make_float4(0, 0, 0, 0);
                we[k] = 0.0f;
            }
        }

        #pragma unroll
        for (int k = 0; k < 4; k++) {
            float d0 = a[k].x - b[k].x;
            float d1 = a[k].y - b[k].y;
            float d2 = a[k].z - b[k].z;
            float d3 = a[k].w - b[k].w;
            float acc = d0 * d0;
            acc = fmaf(d1, d1, acc);
            acc = fmaf(d2, d2, acc);
            acc = fmaf(d3, d3, acc);
            // quad reduce (lanes differ only in lane4 bits)
            acc += __shfl_xor_sync(0xFFFFFFFFu, acc, 1);
            acc += __shfl_xor_sync(0xFFFFFFFFu, acc, 2);
            if (lane4 == 0) val += sqrtf(acc) * we[k];
        }
    }

    // ---- block reduce + finalize ----------------------------------------------
    #pragma unroll
    for (int o = 16; o > 0; o >>= 1)
        val += __shfl_down_sync(0xFFFFFFFFu, val, o);

    __shared__ float s_warp[NTHREADS / 32];
    int lane = threadIdx.x & 31;
    int warp = threadIdx.x >> 5;
    if (lane == 0) s_warp[warp] = val;
    __syncthreads();

    if (warp == 0) {
        val = (lane < NTHREADS / 32) ? s_warp[lane] : 0.0f;
        #pragma unroll
        for (int o = 4; o > 0; o >>= 1)
            val += __shfl_down_sync(0xFFFFFFFFu, val, o);
        if (lane == 0) {
            atomicAdd(&g_sum, (double)val);
            __threadfence();
            unsigned ticket = atomicInc(&g_count, 0xFFFFFFFFu);
            if (ticket == (unsigned)(gridDim.x - 1)) {
                *out = (float)(g_sum / (double)E);
                g_sum  = 0.0;     // restore invariants for next graph replay
                g_count = 0u;
                g_bar1 = 0u;
                g_bar2 = 0u;
            }
        }
    }
}

extern "C" void kernel_launch(void* const* d_in, const int* in_sizes, int n_in,
                              void* d_out, int out_size) {
    const void*   ei  = d_in[0];
    const float*  w   = (const float*)d_in[1];
    const float4* y4  = (const float4*)d_in[2];
    float*        out = (float*)d_out;

    const int E = in_sizes[1];       // number of edges
    const int N = in_sizes[2] / 16;  // number of nodes

    int ntiles = (E + EDGES_PER_TILE - 1) / EDGES_PER_TILE;

    k_fused<<<NBLOCKS, NTHREADS>>>(ei, w, y4, out, E, N, ntiles);
}